// round 1
// baseline (speedup 1.0000x reference)
#include <cuda_runtime.h>
#include <math.h>

#define BATCH 16
#define NPTS  2048
#define DIM   128
#define TILE  128
#define KCHUNK 32

// Scratch (no device allocation allowed -> __device__ globals)
__device__ float g_sqnorms[BATCH * NPTS];
__device__ float g_nnd[BATCH * NPTS];

// ---------------------------------------------------------------------------
// Kernel 1: squared norms, one warp per row (coalesced float4 loads)
// ---------------------------------------------------------------------------
__global__ void sqnorm_kernel(const float* __restrict__ x) {
    int warp_id = (blockIdx.x * blockDim.x + threadIdx.x) >> 5;
    int lane    = threadIdx.x & 31;
    if (warp_id >= BATCH * NPTS) return;
    const float4* row = (const float4*)(x + (size_t)warp_id * DIM);
    float4 v = row[lane];                       // 32 lanes * 4 = 128 elems
    float s = v.x * v.x + v.y * v.y + v.z * v.z + v.w * v.w;
    #pragma unroll
    for (int o = 16; o; o >>= 1) s += __shfl_xor_sync(0xffffffffu, s, o);
    if (lane == 0) g_sqnorms[warp_id] = s;
}

// ---------------------------------------------------------------------------
// Kernel 2: tiled GEMM + running row-min of (||xj||^2 - 2 xi.xj)
// Grid: (NPTS/TILE, BATCH). 256 threads, 8x8 register tile, cyclic mapping:
//   rows = ty + 16*r, cols = tx + 16*c  (conflict-free smem reads)
// Smem k-major [KCHUNK][TILE+1]: transpose-store banks = (4*kq + row) % 32
// -> all 32 banks distinct within a warp (conflict-free stores).
// ---------------------------------------------------------------------------
__global__ __launch_bounds__(256, 2)
void nnd_kernel(const float* __restrict__ x) {
    __shared__ float As[KCHUNK][TILE + 1];
    __shared__ float Bs[KCHUNK][TILE + 1];

    const int b   = blockIdx.y;
    const int r0  = blockIdx.x * TILE;
    const int tid = threadIdx.x;
    const int tx  = tid & 15;
    const int ty  = tid >> 4;
    const float* X = x + (size_t)b * NPTS * DIM;

    float rmin[8];
    #pragma unroll
    for (int r = 0; r < 8; r++) rmin[r] = 3.4e38f;

    for (int j0 = 0; j0 < NPTS; j0 += TILE) {
        float acc[8][8];
        #pragma unroll
        for (int r = 0; r < 8; r++)
            #pragma unroll
            for (int c = 0; c < 8; c++) acc[r][c] = 0.0f;

        for (int k0 = 0; k0 < DIM; k0 += KCHUNK) {
            __syncthreads();
            // Load A chunk (rows r0..r0+127) and B chunk (rows j0..j0+127),
            // k in [k0, k0+32). 1024 float4 per tile, 4 per thread.
            #pragma unroll
            for (int it = 0; it < 4; it++) {
                int i   = tid + 256 * it;      // float4 index 0..1023
                int row = i >> 3;              // 0..127
                int kq  = i & 7;               // float4 slot along k
                float4 v = *(const float4*)(X + (size_t)(r0 + row) * DIM + k0 + kq * 4);
                As[kq * 4 + 0][row] = v.x;
                As[kq * 4 + 1][row] = v.y;
                As[kq * 4 + 2][row] = v.z;
                As[kq * 4 + 3][row] = v.w;
                float4 w = *(const float4*)(X + (size_t)(j0 + row) * DIM + k0 + kq * 4);
                Bs[kq * 4 + 0][row] = w.x;
                Bs[kq * 4 + 1][row] = w.y;
                Bs[kq * 4 + 2][row] = w.z;
                Bs[kq * 4 + 3][row] = w.w;
            }
            __syncthreads();

            #pragma unroll 8
            for (int kk = 0; kk < KCHUNK; kk++) {
                float a[8], bb[8];
                #pragma unroll
                for (int r = 0; r < 8; r++) a[r]  = As[kk][ty + 16 * r];
                #pragma unroll
                for (int c = 0; c < 8; c++) bb[c] = Bs[kk][tx + 16 * c];
                #pragma unroll
                for (int r = 0; r < 8; r++)
                    #pragma unroll
                    for (int c = 0; c < 8; c++)
                        acc[r][c] = fmaf(a[r], bb[c], acc[r][c]);
            }
        }

        // Epilogue: fold ||xj||^2 - 2*dot into the running row-min (diag masked)
        #pragma unroll
        for (int c = 0; c < 8; c++) {
            int gc   = j0 + tx + 16 * c;
            float qj = g_sqnorms[b * NPTS + gc];
            #pragma unroll
            for (int r = 0; r < 8; r++) {
                int gr = r0 + ty + 16 * r;
                float cand = fmaf(-2.0f, acc[r][c], qj);
                if (gr != gc) rmin[r] = fminf(rmin[r], cand);
            }
        }
    }

    // Reduce min across the 16 tx-threads sharing each row (half-warp shuffle)
    #pragma unroll
    for (int r = 0; r < 8; r++) {
        float v = rmin[r];
        #pragma unroll
        for (int o = 8; o; o >>= 1) v = fminf(v, __shfl_xor_sync(0xffffffffu, v, o));
        if (tx == 0) {
            int gr   = r0 + ty + 16 * r;
            float qi = g_sqnorms[b * NPTS + gr];
            float sq = fmaxf(qi + v, 0.0f);
            g_nnd[b * NPTS + gr] = sqrtf(sq);
        }
    }
}

// ---------------------------------------------------------------------------
// Kernel 3: mean / std(ddof=1) / cv over 32768 NND values (double accum)
// ---------------------------------------------------------------------------
__global__ void finalize_kernel(float* __restrict__ out) {
    const int tid = threadIdx.x;
    double s = 0.0, q = 0.0;
    for (int i = tid; i < BATCH * NPTS; i += 1024) {
        double v = (double)g_nnd[i];
        s += v;
        q += v * v;
    }
    #pragma unroll
    for (int o = 16; o; o >>= 1) {
        s += __shfl_xor_sync(0xffffffffu, s, o);
        q += __shfl_xor_sync(0xffffffffu, q, o);
    }
    __shared__ double ss[32], sq[32];
    int w = tid >> 5, l = tid & 31;
    if (l == 0) { ss[w] = s; sq[w] = q; }
    __syncthreads();
    if (w == 0) {
        s = ss[l];
        q = sq[l];
        #pragma unroll
        for (int o = 16; o; o >>= 1) {
            s += __shfl_xor_sync(0xffffffffu, s, o);
            q += __shfl_xor_sync(0xffffffffu, q, o);
        }
        if (l == 0) {
            const double n = (double)(BATCH * NPTS);
            double mean = s / n;
            double var  = (q - s * s / n) / (n - 1.0);
            double sd   = sqrt(var > 0.0 ? var : 0.0);
            double cv   = (mean > 1e-8) ? sd / mean : 0.0;
            out[0] = (float)mean;
            out[1] = (float)sd;
            out[2] = (float)cv;
        }
    }
}

// ---------------------------------------------------------------------------
extern "C" void kernel_launch(void* const* d_in, const int* in_sizes, int n_in,
                              void* d_out, int out_size) {
    const float* x = (const float*)d_in[0];
    float* out = (float*)d_out;

    // Kernel 1: 32768 rows, one warp each -> 32768*32 threads
    sqnorm_kernel<<<(BATCH * NPTS * 32 + 255) / 256, 256>>>(x);

    // Kernel 2: 16 row-tiles x 16 batches
    dim3 grid(NPTS / TILE, BATCH);
    nnd_kernel<<<grid, 256>>>(x);

    // Kernel 3: single CTA finalize
    finalize_kernel<<<1, 1024>>>(out);
}

// round 2
// speedup vs baseline: 1.1880x; 1.1880x over previous
#include <cuda_runtime.h>
#include <math.h>

#define BATCH 16
#define NPTS  2048
#define DIM   128
#define TILE  128
#define KCHUNK 32

typedef unsigned long long u64;

// Scratch (no device allocation allowed -> __device__ globals)
__device__ float g_sqnorms[BATCH * NPTS];
__device__ float g_nnd[BATCH * NPTS];

__device__ __forceinline__ u64 pack2(float lo, float hi) {
    u64 v; asm("mov.b64 %0, {%1, %2};" : "=l"(v) : "f"(lo), "f"(hi)); return v;
}
__device__ __forceinline__ u64 dup2(float x) {
    u64 v; asm("mov.b64 %0, {%1, %1};" : "=l"(v) : "f"(x)); return v;
}
__device__ __forceinline__ void unpack2(u64 v, float& lo, float& hi) {
    asm("mov.b64 {%0, %1}, %2;" : "=f"(lo), "=f"(hi) : "l"(v));
}
__device__ __forceinline__ void ffma2(u64& d, u64 a, u64 b) {
    asm("fma.rn.f32x2 %0, %1, %2, %0;" : "+l"(d) : "l"(a), "l"(b));
}

// ---------------------------------------------------------------------------
// Kernel 1: squared norms, one warp per row (coalesced float4 loads)
// ---------------------------------------------------------------------------
__global__ void sqnorm_kernel(const float* __restrict__ x) {
    int warp_id = (blockIdx.x * blockDim.x + threadIdx.x) >> 5;
    int lane    = threadIdx.x & 31;
    if (warp_id >= BATCH * NPTS) return;
    const float4* row = (const float4*)(x + (size_t)warp_id * DIM);
    float4 v = row[lane];                       // 32 lanes * 4 = 128 elems
    float s = v.x * v.x + v.y * v.y + v.z * v.z + v.w * v.w;
    #pragma unroll
    for (int o = 16; o; o >>= 1) s += __shfl_xor_sync(0xffffffffu, s, o);
    if (lane == 0) g_sqnorms[warp_id] = s;
}

// ---------------------------------------------------------------------------
// Kernel 2: tiled GEMM + running row-min of (||xj||^2 - 2 xi.xj)
// Grid: (NPTS/TILE, BATCH). 256 threads, 8x8 register tile, cyclic mapping:
//   rows = ty + 16*r, cols = tx + 16*c  (conflict-free smem reads)
// Packed-fp32 mainloop: rows paired (r=2p, 2p+1) into f32x2 lanes,
// fma.rn.f32x2 (SASS FFMA2) halves the FMA-pipe instruction count.
// ---------------------------------------------------------------------------
__global__ __launch_bounds__(256, 2)
void nnd_kernel(const float* __restrict__ x) {
    __shared__ float As[KCHUNK][TILE + 1];
    __shared__ float Bs[KCHUNK][TILE + 1];

    const int b   = blockIdx.y;
    const int r0  = blockIdx.x * TILE;
    const int tid = threadIdx.x;
    const int tx  = tid & 15;
    const int ty  = tid >> 4;
    const float* X = x + (size_t)b * NPTS * DIM;

    float rmin[8];
    #pragma unroll
    for (int r = 0; r < 8; r++) rmin[r] = 3.4e38f;

    for (int j0 = 0; j0 < NPTS; j0 += TILE) {
        u64 accp[4][8];                         // row-pair p, col c
        #pragma unroll
        for (int p = 0; p < 4; p++)
            #pragma unroll
            for (int c = 0; c < 8; c++) accp[p][c] = 0ull;  // (+0.f, +0.f)

        for (int k0 = 0; k0 < DIM; k0 += KCHUNK) {
            __syncthreads();
            // Load A chunk (rows r0..r0+127) and B chunk (rows j0..j0+127),
            // k in [k0, k0+32). 1024 float4 per tile, 4 per thread.
            #pragma unroll
            for (int it = 0; it < 4; it++) {
                int i   = tid + 256 * it;      // float4 index 0..1023
                int row = i >> 3;              // 0..127
                int kq  = i & 7;               // float4 slot along k
                float4 v = *(const float4*)(X + (size_t)(r0 + row) * DIM + k0 + kq * 4);
                As[kq * 4 + 0][row] = v.x;
                As[kq * 4 + 1][row] = v.y;
                As[kq * 4 + 2][row] = v.z;
                As[kq * 4 + 3][row] = v.w;
                float4 w = *(const float4*)(X + (size_t)(j0 + row) * DIM + k0 + kq * 4);
                Bs[kq * 4 + 0][row] = w.x;
                Bs[kq * 4 + 1][row] = w.y;
                Bs[kq * 4 + 2][row] = w.z;
                Bs[kq * 4 + 3][row] = w.w;
            }
            __syncthreads();

            #pragma unroll 8
            for (int kk = 0; kk < KCHUNK; kk++) {
                float a0[8];
                u64 ap[4], bp[8];
                #pragma unroll
                for (int r = 0; r < 8; r++) a0[r] = As[kk][ty + 16 * r];
                #pragma unroll
                for (int p = 0; p < 4; p++) ap[p] = pack2(a0[2 * p], a0[2 * p + 1]);
                #pragma unroll
                for (int c = 0; c < 8; c++) bp[c] = dup2(Bs[kk][tx + 16 * c]);
                #pragma unroll
                for (int p = 0; p < 4; p++)
                    #pragma unroll
                    for (int c = 0; c < 8; c++)
                        ffma2(accp[p][c], ap[p], bp[c]);
            }
        }

        // Epilogue: fold ||xj||^2 - 2*dot into the running row-min (diag masked)
        #pragma unroll
        for (int c = 0; c < 8; c++) {
            int gc   = j0 + tx + 16 * c;
            float qj = g_sqnorms[b * NPTS + gc];
            #pragma unroll
            for (int p = 0; p < 4; p++) {
                float d0, d1;
                unpack2(accp[p][c], d0, d1);
                int gr0 = r0 + ty + 16 * (2 * p);       // r = 2p
                int gr1 = r0 + ty + 16 * (2 * p + 1);   // r = 2p+1
                float c0 = fmaf(-2.0f, d0, qj);
                float c1 = fmaf(-2.0f, d1, qj);
                if (gr0 != gc) rmin[2 * p]     = fminf(rmin[2 * p],     c0);
                if (gr1 != gc) rmin[2 * p + 1] = fminf(rmin[2 * p + 1], c1);
            }
        }
    }

    // Reduce min across the 16 tx-threads sharing each row (half-warp shuffle)
    #pragma unroll
    for (int r = 0; r < 8; r++) {
        float v = rmin[r];
        #pragma unroll
        for (int o = 8; o; o >>= 1) v = fminf(v, __shfl_xor_sync(0xffffffffu, v, o));
        if (tx == 0) {
            int gr   = r0 + ty + 16 * r;
            float qi = g_sqnorms[b * NPTS + gr];
            float sq = fmaxf(qi + v, 0.0f);
            g_nnd[b * NPTS + gr] = sqrtf(sq);
        }
    }
}

// ---------------------------------------------------------------------------
// Kernel 3: mean / std(ddof=1) / cv over 32768 NND values (double accum)
// ---------------------------------------------------------------------------
__global__ void finalize_kernel(float* __restrict__ out) {
    const int tid = threadIdx.x;
    double s = 0.0, q = 0.0;
    for (int i = tid; i < BATCH * NPTS; i += 1024) {
        double v = (double)g_nnd[i];
        s += v;
        q += v * v;
    }
    #pragma unroll
    for (int o = 16; o; o >>= 1) {
        s += __shfl_xor_sync(0xffffffffu, s, o);
        q += __shfl_xor_sync(0xffffffffu, q, o);
    }
    __shared__ double ss[32], sq[32];
    int w = tid >> 5, l = tid & 31;
    if (l == 0) { ss[w] = s; sq[w] = q; }
    __syncthreads();
    if (w == 0) {
        s = ss[l];
        q = sq[l];
        #pragma unroll
        for (int o = 16; o; o >>= 1) {
            s += __shfl_xor_sync(0xffffffffu, s, o);
            q += __shfl_xor_sync(0xffffffffu, q, o);
        }
        if (l == 0) {
            const double n = (double)(BATCH * NPTS);
            double mean = s / n;
            double var  = (q - s * s / n) / (n - 1.0);
            double sd   = sqrt(var > 0.0 ? var : 0.0);
            double cv   = (mean > 1e-8) ? sd / mean : 0.0;
            out[0] = (float)mean;
            out[1] = (float)sd;
            out[2] = (float)cv;
        }
    }
}

// ---------------------------------------------------------------------------
extern "C" void kernel_launch(void* const* d_in, const int* in_sizes, int n_in,
                              void* d_out, int out_size) {
    const float* x = (const float*)d_in[0];
    float* out = (float*)d_out;

    // Kernel 1: 32768 rows, one warp each -> 32768*32 threads
    sqnorm_kernel<<<(BATCH * NPTS * 32 + 255) / 256, 256>>>(x);

    // Kernel 2: 16 row-tiles x 16 batches
    dim3 grid(NPTS / TILE, BATCH);
    nnd_kernel<<<grid, 256>>>(x);

    // Kernel 3: single CTA finalize
    finalize_kernel<<<1, 1024>>>(out);
}

// round 4
// speedup vs baseline: 2.7525x; 2.3170x over previous
#include <cuda_runtime.h>
#include <cuda_bf16.h>
#include <math.h>
#include <cstdint>

#define BATCH 16
#define NPTS  2048
#define DIM   128
#define TILE  128
#define NJT   (NPTS / TILE)    // 16

// ---------------- scratch (no runtime allocation allowed) -------------------
__device__ float         g_sqnorms[BATCH * NPTS];
__device__ float         g_nnd[BATCH * NPTS];
__device__ __nv_bfloat16 g_hi[BATCH * NPTS * DIM];   // 8 MB
__device__ __nv_bfloat16 g_lo[BATCH * NPTS * DIM];   // 8 MB

// ---------------- smem layout (bytes): rows are 256B (128 bf16) -------------
#define SM_QS   0                    // 2048 floats = 8192 B
#define SM_AH   8192                 // 128x128 bf16 = 32768 B
#define SM_AL   40960
#define SM_B0H  73728                // B double buffers (hi/lo x 2)
#define SM_B0L  106496
#define SM_B1H  139264
#define SM_B1L  172032
#define SM_RED  73728                // reduction scratch reuses B0H after loop
#define SMEM_TOTAL 204800            // 200 KB

// swizzle for 256B rows: XOR 16B-chunk index (bits 4..6) with row low bits
__device__ __forceinline__ uint32_t swz(uint32_t off) {
    return off ^ ((off >> 4) & 0x70);
}

__device__ __forceinline__ uint32_t smem_u32(const void* p) {
    uint32_t a;
    asm("{ .reg .u64 t; cvta.to.shared.u64 t, %1; cvt.u32.u64 %0, t; }"
        : "=r"(a) : "l"(p));
    return a;
}

__device__ __forceinline__ void cp16(uint32_t dst, const void* src) {
    asm volatile("cp.async.ca.shared.global [%0], [%1], 16;" :: "r"(dst), "l"(src));
}
#define CP_COMMIT() asm volatile("cp.async.commit_group;" ::: "memory")
#define CP_WAIT0()  asm volatile("cp.async.wait_group 0;" ::: "memory")

__device__ __forceinline__ void ldsm_x4(unsigned* r, uint32_t addr) {
    asm volatile("ldmatrix.sync.aligned.m8n8.x4.shared.b16 {%0,%1,%2,%3}, [%4];"
        : "=r"(r[0]), "=r"(r[1]), "=r"(r[2]), "=r"(r[3]) : "r"(addr));
}
__device__ __forceinline__ void ldsm_x2(unsigned* r, uint32_t addr) {
    asm volatile("ldmatrix.sync.aligned.m8n8.x2.shared.b16 {%0,%1}, [%2];"
        : "=r"(r[0]), "=r"(r[1]) : "r"(addr));
}
__device__ __forceinline__ void mma16816(float* d, const unsigned* a, const unsigned* b) {
    asm volatile(
        "mma.sync.aligned.m16n8k16.row.col.f32.bf16.bf16.f32 "
        "{%0,%1,%2,%3}, {%4,%5,%6,%7}, {%8,%9}, {%0,%1,%2,%3};"
        : "+f"(d[0]), "+f"(d[1]), "+f"(d[2]), "+f"(d[3])
        : "r"(a[0]), "r"(a[1]), "r"(a[2]), "r"(a[3]), "r"(b[0]), "r"(b[1]));
}

// cp.async a 128x128 bf16 tile (row-major global) into swizzled smem
__device__ __forceinline__ void cp_tile(uint32_t smem_u, uint32_t off,
                                        const __nv_bfloat16* g, int row0, int tid) {
    const uint4* src = (const uint4*)(g + (size_t)row0 * DIM);
    #pragma unroll
    for (int it = 0; it < 8; it++) {
        int idx = tid + 256 * it;                // uint4 index; 16 per row
        uint32_t boff = (uint32_t)idx * 16u;     // row*256 + chunk*16
        cp16(smem_u + off + swz(boff), src + idx);
    }
}

// ---------------------------------------------------------------------------
// Kernel 1: per-row sqnorm + bf16 hi/lo split planes
// ---------------------------------------------------------------------------
__global__ void prep_kernel(const float* __restrict__ x) {
    int warp_id = (blockIdx.x * blockDim.x + threadIdx.x) >> 5;
    int lane    = threadIdx.x & 31;
    if (warp_id >= BATCH * NPTS) return;
    float4 v = ((const float4*)(x + (size_t)warp_id * DIM))[lane];
    float s = v.x * v.x + v.y * v.y + v.z * v.z + v.w * v.w;
    #pragma unroll
    for (int o = 16; o; o >>= 1) s += __shfl_xor_sync(0xffffffffu, s, o);

    __nv_bfloat16 h0 = __float2bfloat16(v.x);
    __nv_bfloat16 h1 = __float2bfloat16(v.y);
    __nv_bfloat16 h2 = __float2bfloat16(v.z);
    __nv_bfloat16 h3 = __float2bfloat16(v.w);
    __nv_bfloat16 l0 = __float2bfloat16(v.x - __bfloat162float(h0));
    __nv_bfloat16 l1 = __float2bfloat16(v.y - __bfloat162float(h1));
    __nv_bfloat16 l2 = __float2bfloat16(v.z - __bfloat162float(h2));
    __nv_bfloat16 l3 = __float2bfloat16(v.w - __bfloat162float(h3));

    __nv_bfloat162* ph = (__nv_bfloat162*)g_hi;
    __nv_bfloat162* pl = (__nv_bfloat162*)g_lo;
    int base = warp_id * 64 + lane * 2;
    ph[base]     = __halves2bfloat162(h0, h1);
    ph[base + 1] = __halves2bfloat162(h2, h3);
    pl[base]     = __halves2bfloat162(l0, l1);
    pl[base + 1] = __halves2bfloat162(l2, l3);

    if (lane == 0) g_sqnorms[warp_id] = s;
}

// ---------------------------------------------------------------------------
// Kernel 2: split-bf16 HMMA Gram + per-row running min epilogue
// Grid (16 i-tiles, 16 batches), 256 threads = 8 warps (2 x 4).
// Warp tile 64x32 via mma.m16n8k16 (4 m-tiles x 4 n-tiles).
// ---------------------------------------------------------------------------
__global__ __launch_bounds__(256, 1)
void nnd_hmma_kernel() {
    extern __shared__ char smem[];
    const int tid  = threadIdx.x;
    const int wid  = tid >> 5;
    const int lane = tid & 31;
    const int wm   = wid >> 2;         // 0..1  (64-row band)
    const int wn   = wid & 3;          // 0..3  (32-col band)
    const int b    = blockIdx.y;
    const int i0   = blockIdx.x * TILE;
    const uint32_t smem_u = smem_u32(smem);

    // ldmatrix lane decomposition
    const int r8   = lane & 7;
    const int q    = lane >> 3;        // 0..3  (A x4 quads)
    const int l15  = lane & 15;
    const int rb   = l15 & 7;          // B x2 rows
    const int hb   = l15 >> 3;         // B x2 half (k +8)
    const int g    = lane >> 2;        // mma group row
    const int t    = lane & 3;         // mma thread-in-group

    const __nv_bfloat16* Hb = g_hi + (size_t)b * NPTS * DIM;
    const __nv_bfloat16* Lb = g_lo + (size_t)b * NPTS * DIM;

    // initial stage: qs + A(hi/lo) + B tile 0 (hi/lo)
    {
        const uint4* qsrc = (const uint4*)(g_sqnorms + b * NPTS);
        cp16(smem_u + SM_QS + tid * 16u, qsrc + tid);
        cp16(smem_u + SM_QS + 4096u + tid * 16u, qsrc + 256 + tid);
    }
    cp_tile(smem_u, SM_AH, Hb, i0, tid);
    cp_tile(smem_u, SM_AL, Lb, i0, tid);
    cp_tile(smem_u, SM_B0H, Hb, 0, tid);
    cp_tile(smem_u, SM_B0L, Lb, 0, tid);
    CP_COMMIT();
    CP_WAIT0();
    __syncthreads();

    const float2* qs2 = (const float2*)(smem + SM_QS);
    const float*  qs  = (const float*)(smem + SM_QS);

    float rmin[8];
    #pragma unroll
    for (int r = 0; r < 8; r++) rmin[r] = 3.4e38f;

    // precompute A ldmatrix base offsets (per m-tile), k part added in loop
    uint32_t a_row = (uint32_t)(wm * 64 + ((q & 1) << 3) + r8);
    uint32_t a_kq  = (uint32_t)((q >> 1) << 4);
    uint32_t b_row = (uint32_t)(wn * 32 + rb);
    uint32_t b_kq  = (uint32_t)(hb << 4);

    for (int jt = 0; jt < NJT; jt++) {
        const uint32_t bh_off = (jt & 1) ? SM_B1H : SM_B0H;
        const uint32_t bl_off = (jt & 1) ? SM_B1L : SM_B0L;

        // prefetch next B tile into the other buffer
        if (jt + 1 < NJT) {
            const uint32_t nh = ((jt + 1) & 1) ? SM_B1H : SM_B0H;
            const uint32_t nl = ((jt + 1) & 1) ? SM_B1L : SM_B0L;
            cp_tile(smem_u, nh, Hb, (jt + 1) * TILE, tid);
            cp_tile(smem_u, nl, Lb, (jt + 1) * TILE, tid);
            CP_COMMIT();
        }

        float d[4][4][4];
        #pragma unroll
        for (int mt = 0; mt < 4; mt++)
            #pragma unroll
            for (int nt = 0; nt < 4; nt++)
                #pragma unroll
                for (int e = 0; e < 4; e++) d[mt][nt][e] = 0.0f;

        #pragma unroll
        for (int ks = 0; ks < 8; ks++) {
            const uint32_t kb = (uint32_t)ks * 32u;
            unsigned ah[4][4], al[4][4];
            #pragma unroll
            for (int mt = 0; mt < 4; mt++) {
                uint32_t off = swz((a_row + (uint32_t)(mt * 16)) * 256u + kb + a_kq);
                ldsm_x4(ah[mt], smem_u + SM_AH + off);
                ldsm_x4(al[mt], smem_u + SM_AL + off);
            }
            unsigned bhf[4][2], blf[4][2];
            #pragma unroll
            for (int nt = 0; nt < 4; nt++) {
                uint32_t off = swz((b_row + (uint32_t)(nt * 8)) * 256u + kb + b_kq);
                ldsm_x2(bhf[nt], smem_u + bh_off + off);
                ldsm_x2(blf[nt], smem_u + bl_off + off);
            }
            #pragma unroll
            for (int mt = 0; mt < 4; mt++)
                #pragma unroll
                for (int nt = 0; nt < 4; nt++) {
                    mma16816(d[mt][nt], ah[mt], bhf[nt]);
                    mma16816(d[mt][nt], ah[mt], blf[nt]);
                    mma16816(d[mt][nt], al[mt], bhf[nt]);
                }
        }

        // epilogue: fold qj - 2*gram into running row mins (diag masked)
        const int jb = jt * TILE;
        #pragma unroll
        for (int nt = 0; nt < 4; nt++) {
            const int colb = wn * 32 + nt * 8;
            float2 qj = qs2[(jb + colb) / 2 + t];
            const int gc0 = jb + colb + 2 * t;
            const int gc1 = gc0 + 1;
            #pragma unroll
            for (int mt = 0; mt < 4; mt++) {
                const int gr0 = i0 + wm * 64 + mt * 16 + g;
                const int gr1 = gr0 + 8;
                float c00 = fmaf(-2.0f, d[mt][nt][0], qj.x);
                float c01 = fmaf(-2.0f, d[mt][nt][1], qj.y);
                float c10 = fmaf(-2.0f, d[mt][nt][2], qj.x);
                float c11 = fmaf(-2.0f, d[mt][nt][3], qj.y);
                if (gr0 != gc0) rmin[2 * mt]     = fminf(rmin[2 * mt],     c00);
                if (gr0 != gc1) rmin[2 * mt]     = fminf(rmin[2 * mt],     c01);
                if (gr1 != gc0) rmin[2 * mt + 1] = fminf(rmin[2 * mt + 1], c10);
                if (gr1 != gc1) rmin[2 * mt + 1] = fminf(rmin[2 * mt + 1], c11);
            }
        }

        CP_WAIT0();
        __syncthreads();
    }

    // reduce over the 4 t-lanes sharing each row
    #pragma unroll
    for (int r = 0; r < 8; r++) {
        rmin[r] = fminf(rmin[r], __shfl_xor_sync(0xffffffffu, rmin[r], 1));
        rmin[r] = fminf(rmin[r], __shfl_xor_sync(0xffffffffu, rmin[r], 2));
    }
    float* red = (float*)(smem + SM_RED);   // [128][4]
    if (t == 0) {
        #pragma unroll
        for (int mt = 0; mt < 4; mt++) {
            int rl0 = wm * 64 + mt * 16 + g;
            red[rl0 * 4 + wn]       = rmin[2 * mt];
            red[(rl0 + 8) * 4 + wn] = rmin[2 * mt + 1];
        }
    }
    __syncthreads();

    if (tid < 128) {
        float m = fminf(fminf(red[tid * 4 + 0], red[tid * 4 + 1]),
                        fminf(red[tid * 4 + 2], red[tid * 4 + 3]));
        float qi = qs[i0 + tid];
        g_nnd[b * NPTS + i0 + tid] = sqrtf(fmaxf(qi + m, 0.0f));
    }
}

// ---------------------------------------------------------------------------
// Kernel 3: mean / std(ddof=1) / cv over 32768 NND values (double accum)
// ---------------------------------------------------------------------------
__global__ void finalize_kernel(float* __restrict__ out) {
    const int tid = threadIdx.x;
    double s = 0.0, q = 0.0;
    for (int i = tid; i < BATCH * NPTS; i += 1024) {
        double v = (double)g_nnd[i];
        s += v;
        q += v * v;
    }
    #pragma unroll
    for (int o = 16; o; o >>= 1) {
        s += __shfl_xor_sync(0xffffffffu, s, o);
        q += __shfl_xor_sync(0xffffffffu, q, o);
    }
    __shared__ double ss[32], sq[32];
    int w = tid >> 5, l = tid & 31;
    if (l == 0) { ss[w] = s; sq[w] = q; }
    __syncthreads();
    if (w == 0) {
        s = ss[l];
        q = sq[l];
        #pragma unroll
        for (int o = 16; o; o >>= 1) {
            s += __shfl_xor_sync(0xffffffffu, s, o);
            q += __shfl_xor_sync(0xffffffffu, q, o);
        }
        if (l == 0) {
            const double n = (double)(BATCH * NPTS);
            double mean = s / n;
            double var  = (q - s * s / n) / (n - 1.0);
            double sd   = sqrt(var > 0.0 ? var : 0.0);
            double cv   = (mean > 1e-8) ? sd / mean : 0.0;
            out[0] = (float)mean;
            out[1] = (float)sd;
            out[2] = (float)cv;
        }
    }
}

// ---------------------------------------------------------------------------
extern "C" void kernel_launch(void* const* d_in, const int* in_sizes, int n_in,
                              void* d_out, int out_size) {
    const float* x = (const float*)d_in[0];
    float* out = (float*)d_out;

    cudaFuncSetAttribute(nnd_hmma_kernel,
                         cudaFuncAttributeMaxDynamicSharedMemorySize, SMEM_TOTAL);

    prep_kernel<<<(BATCH * NPTS * 32 + 255) / 256, 256>>>(x);

    dim3 grid(NPTS / TILE, BATCH);
    nnd_hmma_kernel<<<grid, 256, SMEM_TOTAL>>>();

    finalize_kernel<<<1, 1024>>>(out);
}

// round 5
// speedup vs baseline: 4.0608x; 1.4753x over previous
#include <cuda_runtime.h>
#include <cuda_bf16.h>
#include <math.h>
#include <cstdint>

#define BATCH 16
#define NPTS  2048
#define DIM   128
#define TILE  128
#define NJT   (NPTS / TILE)      // 16
#define NPAIRS (NJT * (NJT + 1) / 2)   // 136

// ---------------- scratch (no runtime allocation allowed) -------------------
__device__ float         g_sqnorms[BATCH * NPTS];
__device__ unsigned int  g_minsq[BATCH * NPTS];      // fp32 bits, atomicMin-able
__device__ __nv_bfloat16 g_hi[BATCH * NPTS * DIM];   // 8 MB
__device__ __nv_bfloat16 g_lo[BATCH * NPTS * DIM];   // 8 MB

// ---------------- smem: 4 stages of (A hi 8K + B hi/lo 16K) -----------------
#define STG_A(s) ((uint32_t)(s) * 24576u)
#define STG_B(s) ((uint32_t)(s) * 24576u + 8192u)
#define SM_RED   98304
#define SMEM_TOTAL (98304 + 3072)

__device__ __forceinline__ uint32_t smem_u32(const void* p) {
    uint32_t a;
    asm("{ .reg .u64 t; cvta.to.shared.u64 t, %1; cvt.u32.u64 %0, t; }"
        : "=r"(a) : "l"(p));
    return a;
}
__device__ __forceinline__ void cp16(uint32_t dst, const void* src) {
    asm volatile("cp.async.ca.shared.global [%0], [%1], 16;" :: "r"(dst), "l"(src));
}
#define CP_COMMIT() asm volatile("cp.async.commit_group;" ::: "memory")

__device__ __forceinline__ void ldsm_x4(unsigned* r, uint32_t addr) {
    asm volatile("ldmatrix.sync.aligned.m8n8.x4.shared.b16 {%0,%1,%2,%3}, [%4];"
        : "=r"(r[0]), "=r"(r[1]), "=r"(r[2]), "=r"(r[3]) : "r"(addr));
}
__device__ __forceinline__ void ldsm_x2(unsigned* r, uint32_t addr) {
    asm volatile("ldmatrix.sync.aligned.m8n8.x2.shared.b16 {%0,%1}, [%2];"
        : "=r"(r[0]), "=r"(r[1]) : "r"(addr));
}
__device__ __forceinline__ void mma16816(float* d, const unsigned* a, const unsigned* b) {
    asm volatile(
        "mma.sync.aligned.m16n8k16.row.col.f32.bf16.bf16.f32 "
        "{%0,%1,%2,%3}, {%4,%5,%6,%7}, {%8,%9}, {%0,%1,%2,%3};"
        : "+f"(d[0]), "+f"(d[1]), "+f"(d[2]), "+f"(d[3])
        : "r"(a[0]), "r"(a[1]), "r"(a[2]), "r"(a[3]), "r"(b[0]), "r"(b[1]));
}

// ---------------------------------------------------------------------------
// Kernel 1: per-row sqnorm + bf16 hi/lo planes + minsq init
// ---------------------------------------------------------------------------
__global__ void prep_kernel(const float* __restrict__ x) {
    int warp_id = (blockIdx.x * blockDim.x + threadIdx.x) >> 5;
    int lane    = threadIdx.x & 31;
    if (warp_id >= BATCH * NPTS) return;
    float4 v = ((const float4*)(x + (size_t)warp_id * DIM))[lane];
    float s = v.x * v.x + v.y * v.y + v.z * v.z + v.w * v.w;
    #pragma unroll
    for (int o = 16; o; o >>= 1) s += __shfl_xor_sync(0xffffffffu, s, o);

    __nv_bfloat16 h0 = __float2bfloat16(v.x);
    __nv_bfloat16 h1 = __float2bfloat16(v.y);
    __nv_bfloat16 h2 = __float2bfloat16(v.z);
    __nv_bfloat16 h3 = __float2bfloat16(v.w);
    __nv_bfloat16 l0 = __float2bfloat16(v.x - __bfloat162float(h0));
    __nv_bfloat16 l1 = __float2bfloat16(v.y - __bfloat162float(h1));
    __nv_bfloat16 l2 = __float2bfloat16(v.z - __bfloat162float(h2));
    __nv_bfloat16 l3 = __float2bfloat16(v.w - __bfloat162float(h3));

    __nv_bfloat162* ph = (__nv_bfloat162*)g_hi;
    __nv_bfloat162* pl = (__nv_bfloat162*)g_lo;
    int base = warp_id * 64 + lane * 2;
    ph[base]     = __halves2bfloat162(h0, h1);
    ph[base + 1] = __halves2bfloat162(h2, h3);
    pl[base]     = __halves2bfloat162(l0, l1);
    pl[base + 1] = __halves2bfloat162(l2, l3);

    if (lane == 0) {
        g_sqnorms[warp_id] = s;
        g_minsq[warp_id]   = 0x7F800000u;   // +inf
    }
}

// ---------------------------------------------------------------------------
// Kernel 2: one 128x128 upper-triangle tile per CTA, 2-term split-bf16 HMMA.
// 8 warps (2x4), warp tile 64x32. Row-side AND col-side mins via atomicMin.
// ---------------------------------------------------------------------------
__global__ __launch_bounds__(256, 1)
void nnd_sym_kernel() {
    extern __shared__ char smem[];
    const int tid  = threadIdx.x;
    const int wid  = tid >> 5;
    const int lane = tid & 31;
    const int wm   = wid >> 2;
    const int wn   = wid & 3;
    const int b    = blockIdx.y;
    const uint32_t smem_u = smem_u32(smem);

    // decode pair index -> (it, jt), jt >= it
    int it = 0, rem = blockIdx.x;
    while (rem >= NJT - it) { rem -= NJT - it; it++; }
    const int jt = it + rem;
    const int i0 = it * TILE, j0 = jt * TILE;
    const bool diag = (it == jt);

    const int r8  = lane & 7;
    const int q   = lane >> 3;
    const int l15 = lane & 15;
    const int rb  = l15 & 7;
    const int hb  = l15 >> 3;
    const int g   = lane >> 2;
    const int t   = lane & 3;

    const __nv_bfloat16* Hb = g_hi + (size_t)b * NPTS * DIM;
    const __nv_bfloat16* Lb = g_lo + (size_t)b * NPTS * DIM;
    const float* qsg = g_sqnorms + b * NPTS;

    // ---- prefetch all 4 k-chunks (A hi plane, B hi+lo planes) ----
    #pragma unroll
    for (int kc = 0; kc < 4; kc++) {
        // A: 512 cp16 (128 rows x 4 chunks), plain 64B rows
        #pragma unroll
        for (int i = 0; i < 2; i++) {
            int idx = tid + 256 * i;
            int row = idx >> 2, cc = idx & 3;
            cp16(smem_u + STG_A(kc) + (uint32_t)(row * 64 + cc * 16),
                 Hb + (size_t)(i0 + row) * DIM + kc * 32 + cc * 8);
        }
        // B: 1024 cp16, 128B rows [hi 64 | lo 64], swizzled
        #pragma unroll
        for (int i = 0; i < 4; i++) {
            int idx = tid + 256 * i;
            int row = idx >> 3, cc = idx & 7;
            const __nv_bfloat16* src = (cc < 4)
                ? Hb + (size_t)(j0 + row) * DIM + kc * 32 + cc * 8
                : Lb + (size_t)(j0 + row) * DIM + kc * 32 + (cc - 4) * 8;
            uint32_t off = (uint32_t)(row * 128 + cc * 16);
            off ^= (off >> 3) & 0x70;
            cp16(smem_u + STG_B(kc) + off, src);
        }
        CP_COMMIT();
    }

    const uint32_t a_row = (uint32_t)(wm * 64 + ((q & 1) << 3) + r8);
    const uint32_t a_kq  = (uint32_t)((q >> 1) << 4);
    const uint32_t b_row = (uint32_t)(wn * 32 + rb);
    const uint32_t b_kq  = (uint32_t)(hb << 4);

    float d[4][4][4];
    #pragma unroll
    for (int mt = 0; mt < 4; mt++)
        #pragma unroll
        for (int nt = 0; nt < 4; nt++)
            #pragma unroll
            for (int e = 0; e < 4; e++) d[mt][nt][e] = 0.0f;

    #pragma unroll
    for (int kc = 0; kc < 4; kc++) {
        if (kc == 0)      asm volatile("cp.async.wait_group 3;" ::: "memory");
        else if (kc == 1) asm volatile("cp.async.wait_group 2;" ::: "memory");
        else if (kc == 2) asm volatile("cp.async.wait_group 1;" ::: "memory");
        else              asm volatile("cp.async.wait_group 0;" ::: "memory");
        __syncthreads();
        const uint32_t sa = smem_u + STG_A(kc);
        const uint32_t sb = smem_u + STG_B(kc);

        #pragma unroll
        for (int s = 0; s < 2; s++) {
            unsigned ah[4][4], bhf[4][2], blf[4][2];
            #pragma unroll
            for (int mt = 0; mt < 4; mt++)
                ldsm_x4(ah[mt], sa + (a_row + (uint32_t)(mt * 16)) * 64u
                                   + (uint32_t)(s * 32) + a_kq);
            #pragma unroll
            for (int nt = 0; nt < 4; nt++) {
                uint32_t off = (b_row + (uint32_t)(nt * 8)) * 128u
                             + (uint32_t)(s * 32) + b_kq;
                uint32_t offl = off + 64u;
                off  ^= (off  >> 3) & 0x70;
                offl ^= (offl >> 3) & 0x70;
                ldsm_x2(bhf[nt], sb + off);
                ldsm_x2(blf[nt], sb + offl);
            }
            #pragma unroll
            for (int mt = 0; mt < 4; mt++)
                #pragma unroll
                for (int nt = 0; nt < 4; nt++) {
                    mma16816(d[mt][nt], ah[mt], bhf[nt]);
                    mma16816(d[mt][nt], ah[mt], blf[nt]);
                }
        }
    }

    // ---- epilogue ----
    float* red_row = (float*)(smem + SM_RED);          // [128][4]
    float* red_col = (float*)(smem + SM_RED + 2048);   // [128][2]

    // row side: min over tile cols of (qj - 2g)
    float rmin[8];
    #pragma unroll
    for (int r = 0; r < 8; r++) rmin[r] = 3.4e38f;
    #pragma unroll
    for (int nt = 0; nt < 4; nt++) {
        const int gc0 = j0 + wn * 32 + nt * 8 + 2 * t;
        const float qjx = qsg[gc0], qjy = qsg[gc0 + 1];
        #pragma unroll
        for (int mt = 0; mt < 4; mt++) {
            const int gr0 = i0 + wm * 64 + mt * 16 + g;
            const int gr1 = gr0 + 8;
            float c00 = fmaf(-2.0f, d[mt][nt][0], qjx);
            float c01 = fmaf(-2.0f, d[mt][nt][1], qjy);
            float c10 = fmaf(-2.0f, d[mt][nt][2], qjx);
            float c11 = fmaf(-2.0f, d[mt][nt][3], qjy);
            if (!diag || gr0 != gc0)     rmin[2*mt]   = fminf(rmin[2*mt],   c00);
            if (!diag || gr0 != gc0 + 1) rmin[2*mt]   = fminf(rmin[2*mt],   c01);
            if (!diag || gr1 != gc0)     rmin[2*mt+1] = fminf(rmin[2*mt+1], c10);
            if (!diag || gr1 != gc0 + 1) rmin[2*mt+1] = fminf(rmin[2*mt+1], c11);
        }
    }
    #pragma unroll
    for (int r = 0; r < 8; r++) {
        rmin[r] = fminf(rmin[r], __shfl_xor_sync(0xffffffffu, rmin[r], 1));
        rmin[r] = fminf(rmin[r], __shfl_xor_sync(0xffffffffu, rmin[r], 2));
    }
    __syncthreads();   // mainloop smem reads done before scratch reuse pattern
    if (t == 0) {
        #pragma unroll
        for (int mt = 0; mt < 4; mt++) {
            int rl = wm * 64 + mt * 16 + g;
            red_row[rl * 4 + wn]       = rmin[2 * mt];
            red_row[(rl + 8) * 4 + wn] = rmin[2 * mt + 1];
        }
    }

    // col side: min over tile rows of (qi - 2g)  (skip for diagonal tiles)
    if (!diag) {
        float cmin[4][2];
        #pragma unroll
        for (int nt = 0; nt < 4; nt++) { cmin[nt][0] = 3.4e38f; cmin[nt][1] = 3.4e38f; }
        #pragma unroll
        for (int mt = 0; mt < 4; mt++) {
            const int gr0 = i0 + wm * 64 + mt * 16 + g;
            const float qi0 = qsg[gr0], qi1 = qsg[gr0 + 8];
            #pragma unroll
            for (int nt = 0; nt < 4; nt++) {
                cmin[nt][0] = fminf(cmin[nt][0], fmaf(-2.0f, d[mt][nt][0], qi0));
                cmin[nt][1] = fminf(cmin[nt][1], fmaf(-2.0f, d[mt][nt][1], qi0));
                cmin[nt][0] = fminf(cmin[nt][0], fmaf(-2.0f, d[mt][nt][2], qi1));
                cmin[nt][1] = fminf(cmin[nt][1], fmaf(-2.0f, d[mt][nt][3], qi1));
            }
        }
        #pragma unroll
        for (int nt = 0; nt < 4; nt++)
            #pragma unroll
            for (int e = 0; e < 2; e++) {
                float v = cmin[nt][e];
                v = fminf(v, __shfl_xor_sync(0xffffffffu, v, 4));
                v = fminf(v, __shfl_xor_sync(0xffffffffu, v, 8));
                v = fminf(v, __shfl_xor_sync(0xffffffffu, v, 16));
                cmin[nt][e] = v;
            }
        if (lane < 4) {
            #pragma unroll
            for (int nt = 0; nt < 4; nt++) {
                int c0 = wn * 32 + nt * 8 + 2 * lane;
                red_col[c0 * 2 + wm]       = cmin[nt][0];
                red_col[(c0 + 1) * 2 + wm] = cmin[nt][1];
            }
        }
    }
    __syncthreads();

    if (tid < 128) {
        float m = fminf(fminf(red_row[tid * 4 + 0], red_row[tid * 4 + 1]),
                        fminf(red_row[tid * 4 + 2], red_row[tid * 4 + 3]));
        float cand = fmaxf(qsg[i0 + tid] + m, 0.0f);
        atomicMin(&g_minsq[b * NPTS + i0 + tid], __float_as_uint(cand));
        if (!diag) {
            float mc = fminf(red_col[tid * 2 + 0], red_col[tid * 2 + 1]);
            float cc = fmaxf(qsg[j0 + tid] + mc, 0.0f);
            atomicMin(&g_minsq[b * NPTS + j0 + tid], __float_as_uint(cc));
        }
    }
}

// ---------------------------------------------------------------------------
// Kernel 3: sqrt + mean / std(ddof=1) / cv (double accum)
// ---------------------------------------------------------------------------
__global__ void finalize_kernel(float* __restrict__ out) {
    const int tid = threadIdx.x;
    double s = 0.0, q = 0.0;
    for (int i = tid; i < BATCH * NPTS; i += 1024) {
        double v = (double)sqrtf(__uint_as_float(g_minsq[i]));
        s += v;
        q += v * v;
    }
    #pragma unroll
    for (int o = 16; o; o >>= 1) {
        s += __shfl_xor_sync(0xffffffffu, s, o);
        q += __shfl_xor_sync(0xffffffffu, q, o);
    }
    __shared__ double ss[32], sq[32];
    int w = tid >> 5, l = tid & 31;
    if (l == 0) { ss[w] = s; sq[w] = q; }
    __syncthreads();
    if (w == 0) {
        s = ss[l];
        q = sq[l];
        #pragma unroll
        for (int o = 16; o; o >>= 1) {
            s += __shfl_xor_sync(0xffffffffu, s, o);
            q += __shfl_xor_sync(0xffffffffu, q, o);
        }
        if (l == 0) {
            const double n = (double)(BATCH * NPTS);
            double mean = s / n;
            double var  = (q - s * s / n) / (n - 1.0);
            double sd   = sqrt(var > 0.0 ? var : 0.0);
            double cv   = (mean > 1e-8) ? sd / mean : 0.0;
            out[0] = (float)mean;
            out[1] = (float)sd;
            out[2] = (float)cv;
        }
    }
}

// ---------------------------------------------------------------------------
extern "C" void kernel_launch(void* const* d_in, const int* in_sizes, int n_in,
                              void* d_out, int out_size) {
    const float* x = (const float*)d_in[0];
    float* out = (float*)d_out;

    cudaFuncSetAttribute(nnd_sym_kernel,
                         cudaFuncAttributeMaxDynamicSharedMemorySize, SMEM_TOTAL);

    prep_kernel<<<(BATCH * NPTS * 32 + 255) / 256, 256>>>(x);

    dim3 grid(NPAIRS, BATCH);
    nnd_sym_kernel<<<grid, 256, SMEM_TOTAL>>>();

    finalize_kernel<<<1, 1024>>>(out);
}

// round 6
// speedup vs baseline: 6.3935x; 1.5745x over previous
#include <cuda_runtime.h>
#include <cuda_bf16.h>
#include <math.h>
#include <cstdint>

#define BATCH 16
#define NPTS  2048
#define DIM   128
#define TILE  128
#define NJT   (NPTS / TILE)            // 16
#define NPAIRS (NJT * (NJT + 1) / 2)   // 136

// ---------------- scratch (no runtime allocation allowed) -------------------
__device__ float         g_sqnorms[BATCH * NPTS];
__device__ unsigned int  g_minsq[BATCH * NPTS];      // fp32 bits, atomicMin
__device__ __nv_bfloat16 g_hi[BATCH * NPTS * DIM];   // 8 MB

// ---------------- smem: A 32K | B 32K | red 3K ------------------------------
#define SM_A   0u
#define SM_B   32768u
#define SM_RED 65536
#define SMEM_TOTAL (65536 + 3072)

// swizzle for 256B rows
__device__ __forceinline__ uint32_t swz(uint32_t off) {
    return off ^ ((off >> 4) & 0x70);
}
__device__ __forceinline__ uint32_t smem_u32(const void* p) {
    uint32_t a;
    asm("{ .reg .u64 t; cvta.to.shared.u64 t, %1; cvt.u32.u64 %0, t; }"
        : "=r"(a) : "l"(p));
    return a;
}
__device__ __forceinline__ void cp16(uint32_t dst, const void* src) {
    asm volatile("cp.async.ca.shared.global [%0], [%1], 16;" :: "r"(dst), "l"(src));
}
__device__ __forceinline__ void ldsm_x4(unsigned* r, uint32_t addr) {
    asm volatile("ldmatrix.sync.aligned.m8n8.x4.shared.b16 {%0,%1,%2,%3}, [%4];"
        : "=r"(r[0]), "=r"(r[1]), "=r"(r[2]), "=r"(r[3]) : "r"(addr));
}
__device__ __forceinline__ void ldsm_x2(unsigned* r, uint32_t addr) {
    asm volatile("ldmatrix.sync.aligned.m8n8.x2.shared.b16 {%0,%1}, [%2];"
        : "=r"(r[0]), "=r"(r[1]) : "r"(addr));
}
__device__ __forceinline__ void mma16816(float* d, const unsigned* a, const unsigned* b) {
    asm volatile(
        "mma.sync.aligned.m16n8k16.row.col.f32.bf16.bf16.f32 "
        "{%0,%1,%2,%3}, {%4,%5,%6,%7}, {%8,%9}, {%0,%1,%2,%3};"
        : "+f"(d[0]), "+f"(d[1]), "+f"(d[2]), "+f"(d[3])
        : "r"(a[0]), "r"(a[1]), "r"(a[2]), "r"(a[3]), "r"(b[0]), "r"(b[1]));
}

// cp.async a 128x128 bf16 tile (row-major global) into swizzled 256B-row smem
__device__ __forceinline__ void cp_tile(uint32_t smem_u, uint32_t off,
                                        const __nv_bfloat16* g, int row0, int tid) {
    const uint4* src = (const uint4*)(g + (size_t)row0 * DIM);
    #pragma unroll
    for (int it = 0; it < 8; it++) {
        int idx = tid + 256 * it;                 // uint4 index; 16 per row
        cp16(smem_u + off + swz((uint32_t)idx * 16u), src + idx);
    }
}

// ---------------------------------------------------------------------------
// Kernel 1: per-row sqnorm + bf16 hi plane + minsq init
// ---------------------------------------------------------------------------
__global__ void prep_kernel(const float* __restrict__ x) {
    int warp_id = (blockIdx.x * blockDim.x + threadIdx.x) >> 5;
    int lane    = threadIdx.x & 31;
    if (warp_id >= BATCH * NPTS) return;
    float4 v = ((const float4*)(x + (size_t)warp_id * DIM))[lane];
    float s = v.x * v.x + v.y * v.y + v.z * v.z + v.w * v.w;
    #pragma unroll
    for (int o = 16; o; o >>= 1) s += __shfl_xor_sync(0xffffffffu, s, o);

    __nv_bfloat162* ph = (__nv_bfloat162*)g_hi;
    int base = warp_id * 64 + lane * 2;
    ph[base]     = __halves2bfloat162(__float2bfloat16(v.x), __float2bfloat16(v.y));
    ph[base + 1] = __halves2bfloat162(__float2bfloat16(v.z), __float2bfloat16(v.w));

    if (lane == 0) {
        g_sqnorms[warp_id] = s;
        g_minsq[warp_id]   = 0x7F800000u;   // +inf
    }
}

// ---------------------------------------------------------------------------
// Kernel 2: one 128x128 upper-triangle tile per CTA, 1-term bf16 HMMA.
// 8 warps (2x4), warp tile 64x32. Single-stage load, barrier-free mainloop.
// Row-side AND col-side mins folded via atomicMin (symmetry).
// ---------------------------------------------------------------------------
__global__ __launch_bounds__(256, 2)
void nnd_sym_kernel() {
    extern __shared__ char smem[];
    const int tid  = threadIdx.x;
    const int lane = tid & 31;
    const int wid  = tid >> 5;
    const int wm   = wid >> 2;
    const int wn   = wid & 3;
    const int b    = blockIdx.y;
    const uint32_t smem_u = smem_u32(smem);

    // decode pair index -> (it, jt), jt >= it
    int it = 0, rem = blockIdx.x;
    while (rem >= NJT - it) { rem -= NJT - it; it++; }
    const int jt = it + rem;
    const int i0 = it * TILE, j0 = jt * TILE;
    const bool diag = (it == jt);

    const int r8  = lane & 7;
    const int q   = lane >> 3;
    const int l15 = lane & 15;
    const int rb  = l15 & 7;
    const int hb  = l15 >> 3;
    const int g   = lane >> 2;
    const int t   = lane & 3;

    const __nv_bfloat16* Hb = g_hi + (size_t)b * NPTS * DIM;
    const float* qsg = g_sqnorms + b * NPTS;

    // ---- single-stage: load whole A and B tiles, one wait, one sync ----
    cp_tile(smem_u, SM_A, Hb, i0, tid);
    if (!diag) cp_tile(smem_u, SM_B, Hb, j0, tid);
    asm volatile("cp.async.commit_group;" ::: "memory");
    asm volatile("cp.async.wait_group 0;" ::: "memory");
    __syncthreads();

    const uint32_t sa = smem_u + SM_A;
    const uint32_t sb = diag ? (smem_u + SM_A) : (smem_u + SM_B);

    const uint32_t a_row = (uint32_t)(wm * 64 + ((q & 1) << 3) + r8);
    const uint32_t a_kq  = (uint32_t)((q >> 1) << 4);
    const uint32_t b_row = (uint32_t)(wn * 32 + rb);
    const uint32_t b_kq  = (uint32_t)(hb << 4);

    float d[4][4][4];
    #pragma unroll
    for (int mt = 0; mt < 4; mt++)
        #pragma unroll
        for (int nt = 0; nt < 4; nt++)
            #pragma unroll
            for (int e = 0; e < 4; e++) d[mt][nt][e] = 0.0f;

    #pragma unroll
    for (int ks = 0; ks < 8; ks++) {
        const uint32_t kb = (uint32_t)ks * 32u;
        unsigned ah[4][4], bf[4][2];
        #pragma unroll
        for (int mt = 0; mt < 4; mt++)
            ldsm_x4(ah[mt], sa + swz((a_row + (uint32_t)(mt * 16)) * 256u + kb + a_kq));
        #pragma unroll
        for (int nt = 0; nt < 4; nt++)
            ldsm_x2(bf[nt], sb + swz((b_row + (uint32_t)(nt * 8)) * 256u + kb + b_kq));
        #pragma unroll
        for (int mt = 0; mt < 4; mt++)
            #pragma unroll
            for (int nt = 0; nt < 4; nt++)
                mma16816(d[mt][nt], ah[mt], bf[nt]);
    }

    // ---- epilogue ----
    float* red_row = (float*)(smem + SM_RED);          // [128][4]
    float* red_col = (float*)(smem + SM_RED + 2048);   // [128][2]

    // row side: min over tile cols of (qj - 2g)
    float rmin[8];
    #pragma unroll
    for (int r = 0; r < 8; r++) rmin[r] = 3.4e38f;
    #pragma unroll
    for (int nt = 0; nt < 4; nt++) {
        const int gc0 = j0 + wn * 32 + nt * 8 + 2 * t;
        const float qjx = qsg[gc0], qjy = qsg[gc0 + 1];
        #pragma unroll
        for (int mt = 0; mt < 4; mt++) {
            const int gr0 = i0 + wm * 64 + mt * 16 + g;
            const int gr1 = gr0 + 8;
            float c00 = fmaf(-2.0f, d[mt][nt][0], qjx);
            float c01 = fmaf(-2.0f, d[mt][nt][1], qjy);
            float c10 = fmaf(-2.0f, d[mt][nt][2], qjx);
            float c11 = fmaf(-2.0f, d[mt][nt][3], qjy);
            if (!diag || gr0 != gc0)     rmin[2*mt]   = fminf(rmin[2*mt],   c00);
            if (!diag || gr0 != gc0 + 1) rmin[2*mt]   = fminf(rmin[2*mt],   c01);
            if (!diag || gr1 != gc0)     rmin[2*mt+1] = fminf(rmin[2*mt+1], c10);
            if (!diag || gr1 != gc0 + 1) rmin[2*mt+1] = fminf(rmin[2*mt+1], c11);
        }
    }
    #pragma unroll
    for (int r = 0; r < 8; r++) {
        rmin[r] = fminf(rmin[r], __shfl_xor_sync(0xffffffffu, rmin[r], 1));
        rmin[r] = fminf(rmin[r], __shfl_xor_sync(0xffffffffu, rmin[r], 2));
    }
    __syncthreads();
    if (t == 0) {
        #pragma unroll
        for (int mt = 0; mt < 4; mt++) {
            int rl = wm * 64 + mt * 16 + g;
            red_row[rl * 4 + wn]       = rmin[2 * mt];
            red_row[(rl + 8) * 4 + wn] = rmin[2 * mt + 1];
        }
    }

    // col side: min over tile rows of (qi - 2g)  (skip for diagonal tiles)
    if (!diag) {
        float cmin[4][2];
        #pragma unroll
        for (int nt = 0; nt < 4; nt++) { cmin[nt][0] = 3.4e38f; cmin[nt][1] = 3.4e38f; }
        #pragma unroll
        for (int mt = 0; mt < 4; mt++) {
            const int gr0 = i0 + wm * 64 + mt * 16 + g;
            const float qi0 = qsg[gr0], qi1 = qsg[gr0 + 8];
            #pragma unroll
            for (int nt = 0; nt < 4; nt++) {
                cmin[nt][0] = fminf(cmin[nt][0], fmaf(-2.0f, d[mt][nt][0], qi0));
                cmin[nt][1] = fminf(cmin[nt][1], fmaf(-2.0f, d[mt][nt][1], qi0));
                cmin[nt][0] = fminf(cmin[nt][0], fmaf(-2.0f, d[mt][nt][2], qi1));
                cmin[nt][1] = fminf(cmin[nt][1], fmaf(-2.0f, d[mt][nt][3], qi1));
            }
        }
        #pragma unroll
        for (int nt = 0; nt < 4; nt++)
            #pragma unroll
            for (int e = 0; e < 2; e++) {
                float v = cmin[nt][e];
                v = fminf(v, __shfl_xor_sync(0xffffffffu, v, 4));
                v = fminf(v, __shfl_xor_sync(0xffffffffu, v, 8));
                v = fminf(v, __shfl_xor_sync(0xffffffffu, v, 16));
                cmin[nt][e] = v;
            }
        if (lane < 4) {
            #pragma unroll
            for (int nt = 0; nt < 4; nt++) {
                int c0 = wn * 32 + nt * 8 + 2 * lane;
                red_col[c0 * 2 + wm]       = cmin[nt][0];
                red_col[(c0 + 1) * 2 + wm] = cmin[nt][1];
            }
        }
    }
    __syncthreads();

    if (tid < 128) {
        float m = fminf(fminf(red_row[tid * 4 + 0], red_row[tid * 4 + 1]),
                        fminf(red_row[tid * 4 + 2], red_row[tid * 4 + 3]));
        float cand = fmaxf(qsg[i0 + tid] + m, 0.0f);
        atomicMin(&g_minsq[b * NPTS + i0 + tid], __float_as_uint(cand));
        if (!diag) {
            float mc = fminf(red_col[tid * 2 + 0], red_col[tid * 2 + 1]);
            float cc = fmaxf(qsg[j0 + tid] + mc, 0.0f);
            atomicMin(&g_minsq[b * NPTS + j0 + tid], __float_as_uint(cc));
        }
    }
}

// ---------------------------------------------------------------------------
// Kernel 3: sqrt + mean / std(ddof=1) / cv (double accum)
// ---------------------------------------------------------------------------
__global__ void finalize_kernel(float* __restrict__ out) {
    const int tid = threadIdx.x;
    double s = 0.0, q = 0.0;
    for (int i = tid; i < BATCH * NPTS; i += 1024) {
        double v = (double)sqrtf(__uint_as_float(g_minsq[i]));
        s += v;
        q += v * v;
    }
    #pragma unroll
    for (int o = 16; o; o >>= 1) {
        s += __shfl_xor_sync(0xffffffffu, s, o);
        q += __shfl_xor_sync(0xffffffffu, q, o);
    }
    __shared__ double ss[32], sq[32];
    int w = tid >> 5, l = tid & 31;
    if (l == 0) { ss[w] = s; sq[w] = q; }
    __syncthreads();
    if (w == 0) {
        s = ss[l];
        q = sq[l];
        #pragma unroll
        for (int o = 16; o; o >>= 1) {
            s += __shfl_xor_sync(0xffffffffu, s, o);
            q += __shfl_xor_sync(0xffffffffu, q, o);
        }
        if (l == 0) {
            const double n = (double)(BATCH * NPTS);
            double mean = s / n;
            double var  = (q - s * s / n) / (n - 1.0);
            double sd   = sqrt(var > 0.0 ? var : 0.0);
            double cv   = (mean > 1e-8) ? sd / mean : 0.0;
            out[0] = (float)mean;
            out[1] = (float)sd;
            out[2] = (float)cv;
        }
    }
}

// ---------------------------------------------------------------------------
extern "C" void kernel_launch(void* const* d_in, const int* in_sizes, int n_in,
                              void* d_out, int out_size) {
    const float* x = (const float*)d_in[0];
    float* out = (float*)d_out;

    cudaFuncSetAttribute(nnd_sym_kernel,
                         cudaFuncAttributeMaxDynamicSharedMemorySize, SMEM_TOTAL);

    prep_kernel<<<(BATCH * NPTS * 32 + 255) / 256, 256>>>(x);

    dim3 grid(NPAIRS, BATCH);
    nnd_sym_kernel<<<grid, 256, SMEM_TOTAL>>>();

    finalize_kernel<<<1, 1024>>>(out);
}